// round 2
// baseline (speedup 1.0000x reference)
#include <cuda_runtime.h>
#include <cuda_bf16.h>
#include <math.h>
#include <stdint.h>

// Problem constants
#define NP_   1024
#define MNP_  4096
#define BS_   4
#define DIM_  512
#define NH_   8
#define DH_   64
#define TOPK_ 32

// Scratch: qh (4096 rows) + kh (16384 rows) + vh (16384 rows), each 512 floats
__device__ float g_scratch[(NP_*BS_ + 2*MNP_*BS_) * DIM_];

// ---------------------------------------------------------------------------
// SGEMM NT: C[m][n] = sum_k A[m][k] * B[n][k] + bias[n]
// A: M x K row-major, B: N x K row-major, C: M x N row-major.
// BM=BN=128, BK=16, 256 threads, 8x8 per-thread tile (2x 4-fragments).
// ---------------------------------------------------------------------------
#define BM 128
#define BN 128
#define BK 16

__global__ __launch_bounds__(256, 2)
void sgemm_nt_bias(const float* __restrict__ A, const float* __restrict__ B,
                   const float* __restrict__ bias, float* __restrict__ C,
                   int M, int N, int K) {
    __shared__ float As[BK][BM];
    __shared__ float Bs[BK][BN];

    const int tid = threadIdx.x;
    const int tx = tid & 15;   // 0..15
    const int ty = tid >> 4;   // 0..15
    const int brow = blockIdx.y * BM;
    const int bcol = blockIdx.x * BN;

    float acc[8][8];
#pragma unroll
    for (int i = 0; i < 8; i++)
#pragma unroll
        for (int j = 0; j < 8; j++) acc[i][j] = 0.f;

    const int f0 = tid * 2;
    for (int kt = 0; kt < K; kt += BK) {
#pragma unroll
        for (int i = 0; i < 2; i++) {
            int f = f0 + i;
            int r  = f >> 2;          // tile row 0..127
            int kk = (f & 3) * 4;     // k offset 0,4,8,12
            float4 a4 = *(const float4*)(A + (size_t)(brow + r) * K + kt + kk);
            As[kk + 0][r] = a4.x; As[kk + 1][r] = a4.y;
            As[kk + 2][r] = a4.z; As[kk + 3][r] = a4.w;
            float4 b4 = *(const float4*)(B + (size_t)(bcol + r) * K + kt + kk);
            Bs[kk + 0][r] = b4.x; Bs[kk + 1][r] = b4.y;
            Bs[kk + 2][r] = b4.z; Bs[kk + 3][r] = b4.w;
        }
        __syncthreads();
#pragma unroll
        for (int k = 0; k < BK; k++) {
            float a[8], b[8];
            *(float4*)&a[0] = *(const float4*)&As[k][ty * 4];
            *(float4*)&a[4] = *(const float4*)&As[k][64 + ty * 4];
            *(float4*)&b[0] = *(const float4*)&Bs[k][tx * 4];
            *(float4*)&b[4] = *(const float4*)&Bs[k][64 + tx * 4];
#pragma unroll
            for (int i = 0; i < 8; i++)
#pragma unroll
                for (int j = 0; j < 8; j++)
                    acc[i][j] = fmaf(a[i], b[j], acc[i][j]);
        }
        __syncthreads();
    }

    // Epilogue with bias
#pragma unroll
    for (int ih = 0; ih < 2; ih++) {
#pragma unroll
        for (int ii = 0; ii < 4; ii++) {
            int r = brow + ih * 64 + ty * 4 + ii;
#pragma unroll
            for (int jh = 0; jh < 2; jh++) {
                int c = bcol + jh * 64 + tx * 4;
                float4 o;
                o.x = acc[ih * 4 + ii][jh * 4 + 0] + bias[c + 0];
                o.y = acc[ih * 4 + ii][jh * 4 + 1] + bias[c + 1];
                o.z = acc[ih * 4 + ii][jh * 4 + 2] + bias[c + 2];
                o.w = acc[ih * 4 + ii][jh * 4 + 3] + bias[c + 3];
                *(float4*)(C + (size_t)r * N + c) = o;
            }
        }
    }
}

// ---------------------------------------------------------------------------
// Sparse attention: one block per (n, b). 8 warps = 8 heads.
// Softmax over the UNIQUE gathered indices (duplicates masked out, matching
// the reference's mask-set semantics).
// ---------------------------------------------------------------------------
__global__ __launch_bounds__(256, 8)
void attn_kernel(const float* __restrict__ qh, const float* __restrict__ kh,
                 const float* __restrict__ vh, const int* __restrict__ rns,
                 float* __restrict__ out) {
    __shared__ float sq[DIM_];
    __shared__ int srow[TOPK_];

    const int n = blockIdx.x;
    const int b = blockIdx.y;
    const int tid = threadIdx.x;
    const int lane = tid & 31;
    const int h = tid >> 5;   // head = warp

    // stage q row and indices
    ((float2*)sq)[tid] = ((const float2*)(qh + (size_t)(n * BS_ + b) * DIM_))[tid];
    if (tid < TOPK_)
        srow[tid] = rns[((size_t)b * NP_ + n) * TOPK_ + tid];
    __syncthreads();

    // dedupe: lane t valid iff no earlier lane has same index
    const int m = srow[lane];
    bool valid = true;
#pragma unroll
    for (int j = 0; j < TOPK_; j++)
        if (j < lane && srow[j] == m) valid = false;

    // score for candidate `lane` in head h
    float s = -INFINITY;
    if (valid) {
        const float4* kp = (const float4*)(kh + ((size_t)m * BS_ + b) * DIM_ + h * DH_);
        const float4* qp = (const float4*)(sq + h * DH_);
        float a = 0.f;
#pragma unroll
        for (int d = 0; d < DH_ / 4; d++) {
            float4 kv = kp[d];
            float4 qv = qp[d];
            a = fmaf(kv.x, qv.x, a);
            a = fmaf(kv.y, qv.y, a);
            a = fmaf(kv.z, qv.z, a);
            a = fmaf(kv.w, qv.w, a);
        }
        s = a * 0.125f;  // 1/sqrt(64)
    }

    // warp softmax over valid lanes
    float mx = s;
#pragma unroll
    for (int o = 16; o; o >>= 1)
        mx = fmaxf(mx, __shfl_xor_sync(0xffffffffu, mx, o));
    float p = valid ? expf(s - mx) : 0.f;
    float sum = p;
#pragma unroll
    for (int o = 16; o; o >>= 1)
        sum += __shfl_xor_sync(0xffffffffu, sum, o);
    const float w = p / sum;

    // output: lane covers d = lane*2, lane*2+1 of this head
    const int vr = valid ? (m * BS_ + b) : -1;
    float2 acc2 = make_float2(0.f, 0.f);
#pragma unroll
    for (int t = 0; t < TOPK_; t++) {
        float wt = __shfl_sync(0xffffffffu, w, t);
        int r   = __shfl_sync(0xffffffffu, vr, t);
        if (r >= 0) {
            float2 vv = *(const float2*)(vh + (size_t)r * DIM_ + h * DH_ + lane * 2);
            acc2.x = fmaf(wt, vv.x, acc2.x);
            acc2.y = fmaf(wt, vv.y, acc2.y);
        }
    }
    *(float2*)(out + (size_t)(n * BS_ + b) * DIM_ + h * DH_ + lane * 2) = acc2;
}

// ---------------------------------------------------------------------------
extern "C" void kernel_launch(void* const* d_in, const int* in_sizes, int n_in,
                              void* d_out, int out_size) {
    const float* q   = (const float*)d_in[0];
    const float* k   = (const float*)d_in[1];
    const float* v   = (const float*)d_in[2];
    const int*   rns = (const int*)d_in[3];
    const float* W1  = (const float*)d_in[4];
    const float* b1  = (const float*)d_in[5];
    const float* W2  = (const float*)d_in[6];
    const float* b2  = (const float*)d_in[7];
    const float* W3  = (const float*)d_in[8];
    const float* b3  = (const float*)d_in[9];
    float* out = (float*)d_out;

    float* scratch = nullptr;
    cudaGetSymbolAddress((void**)&scratch, g_scratch);
    float* qh = scratch;
    float* kh = qh + (size_t)NP_ * BS_ * DIM_;
    float* vh = kh + (size_t)MNP_ * BS_ * DIM_;

    const int Mq = NP_ * BS_;    // 4096
    const int Mk = MNP_ * BS_;   // 16384

    dim3 blk(256);
    sgemm_nt_bias<<<dim3(DIM_ / BN, Mq / BM), blk>>>(q, W1, b1, qh, Mq, DIM_, DIM_);
    sgemm_nt_bias<<<dim3(DIM_ / BN, Mk / BM), blk>>>(k, W2, b2, kh, Mk, DIM_, DIM_);
    sgemm_nt_bias<<<dim3(DIM_ / BN, Mk / BM), blk>>>(v, W3, b3, vh, Mk, DIM_, DIM_);
    attn_kernel<<<dim3(NP_, BS_), blk>>>(qh, kh, vh, rns, out);
}

// round 4
// speedup vs baseline: 2.2403x; 2.2403x over previous
#include <cuda_runtime.h>
#include <cuda_bf16.h>
#include <math.h>
#include <stdint.h>

// Problem constants
#define NP_   1024
#define MNP_  4096
#define BS_   4
#define DIM_  512
#define NH_   8
#define DH_   64
#define TOPK_ 32

#define MROWS_Q  (NP_*BS_)                 // 4096
#define MROWS_KV (MNP_*BS_)                // 16384
#define MTOT     (MROWS_Q + 2*MROWS_KV)    // 36864

// ---------------------------------------------------------------------------
// Scratch (device globals; no allocation allowed)
// ---------------------------------------------------------------------------
__device__ __nv_bfloat16 g_ahi[(size_t)MTOT * DIM_];
__device__ __nv_bfloat16 g_alo[(size_t)MTOT * DIM_];
__device__ __nv_bfloat16 g_whi[3 * DIM_ * DIM_];
__device__ __nv_bfloat16 g_wlo[3 * DIM_ * DIM_];
__device__ float         g_proj[(size_t)MTOT * DIM_];

// ---------------------------------------------------------------------------
// Helpers
// ---------------------------------------------------------------------------
__device__ __forceinline__ uint32_t smem_u32(const void* p) {
    uint32_t a;
    asm("{ .reg .u64 t; cvta.to.shared.u64 t, %1; cvt.u32.u64 %0, t; }"
        : "=r"(a) : "l"(p));
    return a;
}

__device__ __forceinline__ void cp16(uint32_t dst, const void* src) {
    asm volatile("cp.async.cg.shared.global [%0], [%1], 16;\n"
                 :: "r"(dst), "l"(src) : "memory");
}

__device__ __forceinline__ uint32_t swz(uint32_t o) { return o ^ ((o >> 3) & 0x70); }

__device__ __forceinline__ void ldsm4(uint32_t* f, uint32_t addr) {
    asm volatile("ldmatrix.sync.aligned.m8n8.x4.shared.b16 {%0,%1,%2,%3}, [%4];"
                 : "=r"(f[0]), "=r"(f[1]), "=r"(f[2]), "=r"(f[3]) : "r"(addr));
}

__device__ __forceinline__ void mma16816(float* d, const uint32_t* a,
                                         const uint32_t* b) {
    asm volatile(
        "mma.sync.aligned.m16n8k16.row.col.f32.bf16.bf16.f32 "
        "{%0,%1,%2,%3}, {%4,%5,%6,%7}, {%8,%9}, {%0,%1,%2,%3};"
        : "+f"(d[0]), "+f"(d[1]), "+f"(d[2]), "+f"(d[3])
        : "r"(a[0]), "r"(a[1]), "r"(a[2]), "r"(a[3]), "r"(b[0]), "r"(b[1]));
}

// ---------------------------------------------------------------------------
// Split fp32 -> (bf16 hi, bf16 lo)
// ---------------------------------------------------------------------------
__global__ void split_fp32(const float* __restrict__ src,
                           __nv_bfloat16* __restrict__ hi,
                           __nv_bfloat16* __restrict__ lo, int n4) {
    int i = blockIdx.x * blockDim.x + threadIdx.x;
    if (i >= n4) return;
    float4 x = ((const float4*)src)[i];
    float v[4] = {x.x, x.y, x.z, x.w};
    __nv_bfloat16 h[4], l[4];
#pragma unroll
    for (int j = 0; j < 4; j++) {
        h[j] = __float2bfloat16(v[j]);
        l[j] = __float2bfloat16(v[j] - __bfloat162float(h[j]));
    }
    *(uint2*)(hi + 4 * (size_t)i) = *(uint2*)h;
    *(uint2*)(lo + 4 * (size_t)i) = *(uint2*)l;
}

// ---------------------------------------------------------------------------
// mma.sync split-bf16 GEMM: out[m][n] = sum_k A[m][k]*W[n][k] + bias[n]
// Virtual K = 3*512 (hi*hi, hi*lo, lo*hi). Tile 128x128, K-chunk 64 (SW128).
// Grid: x = 4 N-tiles, y = 288 M-tiles (q:0-31, k:32-159, v:160-287).
// 8 warps as 4(m) x 2(n): warp tile 32x64.
// ---------------------------------------------------------------------------
#define KC       64
#define NCHUNK   24
#define STAGES   3
#define A_BYTES  (128 * 128)                 // 16KB
#define B_BYTES  (128 * 128)                 // 16KB
#define STG_B    (A_BYTES + B_BYTES)         // 32KB
#define GEMM_SMEM (STAGES * STG_B)           // 96KB

__global__ __launch_bounds__(256)
void gemm_mma(const __nv_bfloat16* __restrict__ ahi,
              const __nv_bfloat16* __restrict__ alo,
              const __nv_bfloat16* __restrict__ whi,
              const __nv_bfloat16* __restrict__ wlo,
              const float* __restrict__ b1, const float* __restrict__ b2,
              const float* __restrict__ b3, float* __restrict__ out) {
    extern __shared__ __align__(1024) char smem[];
    const uint32_t sbase = smem_u32(smem);
    const int tid = threadIdx.x;
    const int wid = tid >> 5;
    const int lane = tid & 31;
    const int wm = wid & 3;                 // 0..3 : m
    const int wn = wid >> 2;                // 0..1 : n

    const int n0blk = blockIdx.x * 128;     // 0..384
    const int mt = blockIdx.y;              // 0..287
    const int widx = (mt < 32) ? 0 : (mt < 160) ? 1 : 2;
    const float* bias = (widx == 0) ? b1 : (widx == 1) ? b2 : b3;
    const __nv_bfloat16* Whi = whi + (size_t)widx * DIM_ * DIM_;
    const __nv_bfloat16* Wlo = wlo + (size_t)widx * DIM_ * DIM_;
    const size_t arow0 = (size_t)mt * 128;

    float acc[2][8][4];
#pragma unroll
    for (int i = 0; i < 2; i++)
#pragma unroll
        for (int j = 0; j < 8; j++)
#pragma unroll
            for (int r = 0; r < 4; r++) acc[i][j][r] = 0.f;

    // chunk c: term t = c>>3 (0:hi*Whi, 1:hi*Wlo, 2:lo*Whi), k-off = (c&7)*64
    auto load_chunk = [&](int c, int s) {
        const int t  = c >> 3;
        const int kk = (c & 7) * KC;
        const __nv_bfloat16* Ap = (t < 2) ? ahi : alo;
        const __nv_bfloat16* Bp = (t == 1) ? Wlo : Whi;
        const uint32_t a_s = sbase + s * STG_B;
        const uint32_t b_s = a_s + A_BYTES;
#pragma unroll
        for (int i = 0; i < 4; i++) {        // A: 1024 16B units
            int u = tid + (i << 8);
            int r = u >> 3, j = u & 7;
            cp16(a_s + swz(r * 128 + j * 16),
                 Ap + (arow0 + r) * DIM_ + kk + j * 8);
        }
#pragma unroll
        for (int i = 0; i < 4; i++) {        // B: 1024 16B units
            int u = tid + (i << 8);
            int r = u >> 3, j = u & 7;
            cp16(b_s + swz(r * 128 + j * 16),
                 Bp + (size_t)(n0blk + r) * DIM_ + kk + j * 8);
        }
        asm volatile("cp.async.commit_group;\n" ::: "memory");
    };

    load_chunk(0, 0);
    load_chunk(1, 1);

    // per-lane ldmatrix address components (within-tile offsets, pre-swizzled
    // per kstep below)
    const int a_row = wm * 32 + (lane & 15);     // + i*16
    const int a_ch  = (lane >> 4);               // + c0
    const int b_row = wn * 64 + (lane & 7) + ((lane >> 4) << 3);  // + j*16
    const int b_ch  = ((lane >> 3) & 1);         // + c0

#pragma unroll 1
    for (int c = 0; c < NCHUNK; ++c) {
        const int s = c % STAGES;
        if (c == NCHUNK - 1)
            asm volatile("cp.async.wait_group 0;\n" ::: "memory");
        else
            asm volatile("cp.async.wait_group 1;\n" ::: "memory");
        __syncthreads();
        if (c + 2 < NCHUNK) load_chunk(c + 2, (c + 2) % STAGES);

        const uint32_t a_s = sbase + s * STG_B;
        const uint32_t b_s = a_s + A_BYTES;
#pragma unroll
        for (int ks = 0; ks < 4; ks++) {
            const int c0 = ks * 2;
            uint32_t af[2][4];
#pragma unroll
            for (int i = 0; i < 2; i++)
                ldsm4(af[i], a_s + swz((a_row + i * 16) * 128 + (c0 + a_ch) * 16));
            uint32_t bf[4][4];                   // [j]: n-tiles 2j, 2j+1
#pragma unroll
            for (int j = 0; j < 4; j++)
                ldsm4(bf[j], b_s + swz((b_row + j * 16) * 128 + (c0 + b_ch) * 16));
#pragma unroll
            for (int i = 0; i < 2; i++)
#pragma unroll
                for (int j = 0; j < 4; j++) {
                    mma16816(acc[i][2 * j],     af[i], &bf[j][0]);
                    mma16816(acc[i][2 * j + 1], af[i], &bf[j][2]);
                }
        }
    }

    // epilogue: acc[i][j] is m16n8 at rows (wm*32+i*16), cols (wn*64+j*8)
    const int lr = lane >> 2;           // 0..7
    const int lc = (lane & 3) * 2;      // 0,2,4,6
#pragma unroll
    for (int i = 0; i < 2; i++) {
        const size_t row0 = arow0 + wm * 32 + i * 16 + lr;
#pragma unroll
        for (int j = 0; j < 8; j++) {
            const int col = n0blk + wn * 64 + j * 8 + lc;
            const float bx = bias[col], by = bias[col + 1];
            float2 o0 = make_float2(acc[i][j][0] + bx, acc[i][j][1] + by);
            float2 o1 = make_float2(acc[i][j][2] + bx, acc[i][j][3] + by);
            *(float2*)(out + row0 * DIM_ + col) = o0;
            *(float2*)(out + (row0 + 8) * DIM_ + col) = o1;
        }
    }
}

// ---------------------------------------------------------------------------
// Sparse attention: one block per (n, b). 8 warps = 8 heads.
// ---------------------------------------------------------------------------
__global__ __launch_bounds__(256, 8)
void attn_kernel(const float* __restrict__ qh, const float* __restrict__ kh,
                 const float* __restrict__ vh, const int* __restrict__ rns,
                 float* __restrict__ out) {
    __shared__ float sq[DIM_];
    __shared__ int srow[TOPK_];

    const int n = blockIdx.x;
    const int b = blockIdx.y;
    const int tid = threadIdx.x;
    const int lane = tid & 31;
    const int h = tid >> 5;

    ((float2*)sq)[tid] = ((const float2*)(qh + (size_t)(n * BS_ + b) * DIM_))[tid];
    if (tid < TOPK_)
        srow[tid] = rns[((size_t)b * NP_ + n) * TOPK_ + tid];
    __syncthreads();

    const int m = srow[lane];
    bool valid = true;
#pragma unroll
    for (int j = 0; j < TOPK_; j++)
        if (j < lane && srow[j] == m) valid = false;

    float s = -INFINITY;
    if (valid) {
        const float4* kp = (const float4*)(kh + ((size_t)m * BS_ + b) * DIM_ + h * DH_);
        const float4* qp = (const float4*)(sq + h * DH_);
        float a = 0.f;
#pragma unroll
        for (int d = 0; d < DH_ / 4; d++) {
            float4 kv = kp[d];
            float4 qv = qp[d];
            a = fmaf(kv.x, qv.x, a);
            a = fmaf(kv.y, qv.y, a);
            a = fmaf(kv.z, qv.z, a);
            a = fmaf(kv.w, qv.w, a);
        }
        s = a * 0.125f;
    }

    float mx = s;
#pragma unroll
    for (int o = 16; o; o >>= 1)
        mx = fmaxf(mx, __shfl_xor_sync(0xffffffffu, mx, o));
    float p = valid ? expf(s - mx) : 0.f;
    float sum = p;
#pragma unroll
    for (int o = 16; o; o >>= 1)
        sum += __shfl_xor_sync(0xffffffffu, sum, o);
    const float w = p / sum;

    const int vr = valid ? (m * BS_ + b) : -1;
    float2 acc2 = make_float2(0.f, 0.f);
#pragma unroll
    for (int t = 0; t < TOPK_; t++) {
        float wt = __shfl_sync(0xffffffffu, w, t);
        int r = __shfl_sync(0xffffffffu, vr, t);
        if (r >= 0) {
            float2 vv = *(const float2*)(vh + (size_t)r * DIM_ + h * DH_ + lane * 2);
            acc2.x = fmaf(wt, vv.x, acc2.x);
            acc2.y = fmaf(wt, vv.y, acc2.y);
        }
    }
    *(float2*)(out + (size_t)(n * BS_ + b) * DIM_ + h * DH_ + lane * 2) = acc2;
}

// ---------------------------------------------------------------------------
extern "C" void kernel_launch(void* const* d_in, const int* in_sizes, int n_in,
                              void* d_out, int out_size) {
    const float* q   = (const float*)d_in[0];
    const float* k   = (const float*)d_in[1];
    const float* v   = (const float*)d_in[2];
    const int*   rns = (const int*)d_in[3];
    const float* W1  = (const float*)d_in[4];
    const float* b1  = (const float*)d_in[5];
    const float* W2  = (const float*)d_in[6];
    const float* b2  = (const float*)d_in[7];
    const float* W3  = (const float*)d_in[8];
    const float* b3  = (const float*)d_in[9];
    float* out = (float*)d_out;

    __nv_bfloat16 *ahi, *alo, *whi, *wlo;
    float* proj;
    cudaGetSymbolAddress((void**)&ahi, g_ahi);
    cudaGetSymbolAddress((void**)&alo, g_alo);
    cudaGetSymbolAddress((void**)&whi, g_whi);
    cudaGetSymbolAddress((void**)&wlo, g_wlo);
    cudaGetSymbolAddress((void**)&proj, g_proj);

    cudaFuncSetAttribute(gemm_mma, cudaFuncAttributeMaxDynamicSharedMemorySize,
                         GEMM_SMEM);

    const size_t offK = (size_t)MROWS_Q * DIM_;
    const size_t offV = offK + (size_t)MROWS_KV * DIM_;
    const int nq4 = MROWS_Q * DIM_ / 4;
    const int nk4 = MROWS_KV * DIM_ / 4;
    const int nw4 = DIM_ * DIM_ / 4;

    split_fp32<<<nq4 / 256, 256>>>(q, ahi, alo, nq4);
    split_fp32<<<nk4 / 256, 256>>>(k, ahi + offK, alo + offK, nk4);
    split_fp32<<<nk4 / 256, 256>>>(v, ahi + offV, alo + offV, nk4);
    split_fp32<<<nw4 / 256, 256>>>(W1, whi, wlo, nw4);
    split_fp32<<<nw4 / 256, 256>>>(W2, whi + DIM_ * DIM_, wlo + DIM_ * DIM_, nw4);
    split_fp32<<<nw4 / 256, 256>>>(W3, whi + 2 * DIM_ * DIM_, wlo + 2 * DIM_ * DIM_, nw4);

    gemm_mma<<<dim3(4, 288), 256, GEMM_SMEM>>>(ahi, alo, whi, wlo, b1, b2, b3, proj);

    attn_kernel<<<dim3(NP_, BS_), 256>>>(proj, proj + offK, proj + offV, rns, out);
}